// round 10
// baseline (speedup 1.0000x reference)
#include <cuda_runtime.h>
#include <cstdint>

// ---------------- problem constants ----------------
#define IN_SZ    64
#define HID      128
#define OUT_SZ   64
#define NHEAD    16
#define MT       128          // batch rows per rep
#define REPS     4            // 512 rows per CTA
#define NTHREADS 128          // 4 warps; warp = 32 rows x full width

// ---------------- smem layout (u32 offsets; pitches % 8 == 4 -> conflict-free) ----------------
#define XT_U    0             // x tile: 128 rows x 36 u32
#define W1T_U   4608          // W1^T: 128 rows(n) x 36 u32 (64 k halves)
#define W2T_U   9216          // W2^T:  64 rows(n) x 68 u32 (128 k halves)
#define B1S_U   13568         // 128 f32
#define B2S_U   13696         // 64 f32
#define SMEM_U  13760
#define SMEM_BYTES (SMEM_U * 4)   // 55040 B -> 4 CTAs/SM

#define XPB     144           // x / W1T row pitch bytes
#define HPB     272           // W2T row pitch bytes
#define XP      36
#define HP      68

// ---------------- helpers ----------------
__device__ __forceinline__ uint32_t smem_u32(const void* p) {
    uint32_t a;
    asm("{ .reg .u64 t; cvta.to.shared.u64 t, %1; cvt.u32.u64 %0, t; }"
        : "=r"(a) : "l"(p));
    return a;
}

// pack two f32 -> f16x2 (lo = a, hi = b)
__device__ __forceinline__ uint32_t p2(float a, float b) {
    uint32_t r;
    asm("cvt.rn.f16x2.f32 %0, %1, %2;" : "=r"(r) : "f"(b), "f"(a));
    return r;
}

__device__ __forceinline__ void ldsm4(uint4& d, uint32_t addr) {
    asm volatile("ldmatrix.sync.aligned.m8n8.x4.shared.b16 {%0,%1,%2,%3}, [%4];"
                 : "=r"(d.x), "=r"(d.y), "=r"(d.z), "=r"(d.w) : "r"(addr));
}

// D += A * B  (f16 m16n8k16, row.col, fp32 accum)
__device__ __forceinline__ void mma16(float c[4], const uint4 a, uint32_t b0, uint32_t b1) {
    asm volatile(
        "mma.sync.aligned.m16n8k16.row.col.f32.f16.f16.f32 "
        "{%0,%1,%2,%3}, {%4,%5,%6,%7}, {%8,%9}, {%0,%1,%2,%3};\n"
        : "+f"(c[0]), "+f"(c[1]), "+f"(c[2]), "+f"(c[3])
        : "r"(a.x), "r"(a.y), "r"(a.z), "r"(a.w), "r"(b0), "r"(b1));
}

__device__ __forceinline__ float eluf(float v) {
    return v > 0.0f ? v : (__expf(v) - 1.0f);
}

// ---------------- kernel ----------------
__global__ void __launch_bounds__(NTHREADS, 4)
mlp16_kernel(const float* __restrict__ x,
             const float* __restrict__ W1,
             const float* __restrict__ b1,
             const float* __restrict__ W2,
             const float* __restrict__ b2,
             float* __restrict__ out)
{
    extern __shared__ uint32_t sm[];
    float* b1s = reinterpret_cast<float*>(sm + B1S_U);
    float* b2s = reinterpret_cast<float*>(sm + B2S_U);
    const uint32_t sb = smem_u32(sm);

    const int tid = threadIdx.x;
    const int wid = tid >> 5;          // 0..3 : rows [32*wid, +32)
    const int lid = tid & 31;
    const int g   = lid >> 2;          // 0..7
    const int tc  = lid & 3;           // 0..3
    const int head = blockIdx.x;
    const size_t mbase = (size_t)blockIdx.y * (MT * REPS);

    // ldmatrix per-lane address components
    const int arow = (lid & 7) + (lid & 8);          // A row within 16
    const int akb  = (lid & 16);                     // A k-half byte offset
    const int brow = (lid & 7) + ((lid & 16) >> 1);  // B n-row within 16
    const int bkb  = (lid & 8) << 1;                 // B k-half byte offset

    const uint32_t aX  = sb + XT_U  * 4 + (wid * 32 + arow) * XPB + akb;
    const uint32_t bW1 = sb + W1T_U * 4 + brow * XPB + bkb;
    const uint32_t bW2 = sb + W2T_U * 4 + brow * HPB + bkb;

    // ---- biases ----
    b1s[tid] = b1[head * HID + tid];
    if (tid < OUT_SZ) b2s[tid] = b2[head * OUT_SZ + tid];

    // ---- stage W1^T (fp16): row n = tid, k = 0..63 ----
    {
        const float* W1h = W1 + (size_t)head * IN_SZ * HID;
        const int n = tid;
        #pragma unroll
        for (int i4 = 0; i4 < 16; i4++) {
            int k0 = i4 * 4;
            float w0 = W1h[(k0 + 0) * HID + n];
            float w1 = W1h[(k0 + 1) * HID + n];
            float w2 = W1h[(k0 + 2) * HID + n];
            float w3 = W1h[(k0 + 3) * HID + n];
            uint2 u;
            u.x = p2(w0, w1);
            u.y = p2(w2, w3);
            *reinterpret_cast<uint2*>(sm + W1T_U + n * XP + 2 * i4) = u;
        }
    }

    // ---- stage W2^T (fp16): row n = tid&63, k = 0..127 ----
    {
        const float* W2h = W2 + (size_t)head * HID * OUT_SZ;
        const int n = tid & 63;
        const int jh = tid >> 6;           // 0..1
        #pragma unroll
        for (int jj = 0; jj < 16; jj++) {
            int j4 = jh * 16 + jj;
            int k0 = j4 * 4;
            float w0 = W2h[(k0 + 0) * OUT_SZ + n];
            float w1 = W2h[(k0 + 1) * OUT_SZ + n];
            float w2 = W2h[(k0 + 2) * OUT_SZ + n];
            float w3 = W2h[(k0 + 3) * OUT_SZ + n];
            uint2 u;
            u.x = p2(w0, w1);
            u.y = p2(w2, w3);
            *reinterpret_cast<uint2*>(sm + W2T_U + n * HP + 2 * j4) = u;
        }
    }

    #pragma unroll 1
    for (int rep = 0; rep < REPS; rep++) {
        __syncthreads();   // x buffer free (prior-rep GEMM1 reads done; rep0: W-stage done)

        // ---- stage x tile [128 x 64] -> fp16 rows, pitch XP ----
        {
            const float4* xt = reinterpret_cast<const float4*>(
                x + (mbase + (size_t)rep * MT) * IN_SZ);
            #pragma unroll
            for (int it = 0; it < 8; it++) {
                int task = it * NTHREADS + tid;    // 0..1023
                int row = task >> 3;
                int q   = task & 7;
                float4 v0 = xt[row * 16 + 2 * q];
                float4 v1 = xt[row * 16 + 2 * q + 1];
                uint4 u;
                u.x = p2(v0.x, v0.y);
                u.y = p2(v0.z, v0.w);
                u.z = p2(v1.x, v1.y);
                u.w = p2(v1.z, v1.w);
                *reinterpret_cast<uint4*>(sm + XT_U + row * XP + 4 * q) = u;
            }
        }
        __syncthreads();   // x visible

        uint4 A2q[2][8];   // GEMM2 A fragments (built in registers)

        // ---- GEMM1 in four 32-col quarters (register relief) ----
        #pragma unroll
        for (int qr = 0; qr < 4; qr++) {
            float C1[2][4][4];
            #pragma unroll
            for (int mt = 0; mt < 2; mt++)
                #pragma unroll
                for (int t1 = 0; t1 < 4; t1++)
                    #pragma unroll
                    for (int r = 0; r < 4; r++) C1[mt][t1][r] = 0.0f;

            #pragma unroll
            for (int s = 0; s < 4; s++) {          // k16 steps, K=64
                uint4 A0, A1;
                ldsm4(A0, aX + s * 32);
                ldsm4(A1, aX + s * 32 + 16 * XPB);
                #pragma unroll
                for (int tp = 0; tp < 2; tp++) {   // 2 n-tiles per ldsm
                    uint4 Bv;
                    ldsm4(Bv, bW1 + (qr * 32 + tp * 16) * XPB + s * 32);
                    mma16(C1[0][2 * tp],     A0, Bv.x, Bv.y);
                    mma16(C1[0][2 * tp + 1], A0, Bv.z, Bv.w);
                    mma16(C1[1][2 * tp],     A1, Bv.x, Bv.y);
                    mma16(C1[1][2 * tp + 1], A1, Bv.z, Bv.w);
                }
            }

            // epilogue1: bias + ELU -> pack directly into GEMM2 A fragments
            #pragma unroll
            for (int mt = 0; mt < 2; mt++)
                #pragma unroll
                for (int t1 = 0; t1 < 4; t1++) {
                    int col = qr * 32 + t1 * 8 + 2 * tc;
                    float bA = b1s[col], bB = b1s[col + 1];
                    float v0 = eluf(C1[mt][t1][0] + bA);
                    float v1 = eluf(C1[mt][t1][1] + bB);
                    float v2 = eluf(C1[mt][t1][2] + bA);
                    float v3 = eluf(C1[mt][t1][3] + bB);
                    int s2 = qr * 2 + (t1 >> 1);
                    uint32_t lo = p2(v0, v1);     // rows g
                    uint32_t hi = p2(v2, v3);     // rows g+8
                    if ((t1 & 1) == 0) { A2q[mt][s2].x = lo; A2q[mt][s2].y = hi; }
                    else               { A2q[mt][s2].z = lo; A2q[mt][s2].w = hi; }
                }
        }

        // ---- GEMM2: rows [32wid,+32) x all 64 out cols, K=128, A from regs ----
        float C2[2][8][4];
        #pragma unroll
        for (int mt = 0; mt < 2; mt++)
            #pragma unroll
            for (int t2 = 0; t2 < 8; t2++)
                #pragma unroll
                for (int r = 0; r < 4; r++) C2[mt][t2][r] = 0.0f;

        #pragma unroll
        for (int s = 0; s < 8; s++) {
            #pragma unroll
            for (int tp = 0; tp < 4; tp++) {
                uint4 Bv;
                ldsm4(Bv, bW2 + tp * 16 * HPB + s * 32);
                mma16(C2[0][2 * tp],     A2q[0][s], Bv.x, Bv.y);
                mma16(C2[0][2 * tp + 1], A2q[0][s], Bv.z, Bv.w);
                mma16(C2[1][2 * tp],     A2q[1][s], Bv.x, Bv.y);
                mma16(C2[1][2 * tp + 1], A2q[1][s], Bv.z, Bv.w);
            }
        }

        // ---- epilogue2: + b2 -> out[b, head, :] ----
        #pragma unroll
        for (int mt = 0; mt < 2; mt++) {
            const size_t rbase = mbase + (size_t)rep * MT + wid * 32 + mt * 16 + g;
            #pragma unroll
            for (int half = 0; half < 2; half++) {
                const size_t off = (rbase + 8 * half) * (NHEAD * OUT_SZ)
                                 + (size_t)head * OUT_SZ;
                #pragma unroll
                for (int t2 = 0; t2 < 8; t2++) {
                    int col = t2 * 8 + 2 * tc;
                    float2 o;
                    o.x = C2[mt][t2][half * 2 + 0] + b2s[col];
                    o.y = C2[mt][t2][half * 2 + 1] + b2s[col + 1];
                    *reinterpret_cast<float2*>(out + off + col) = o;
                }
            }
        }
    }
}

// ---------------- launch ----------------
extern "C" void kernel_launch(void* const* d_in, const int* in_sizes, int n_in,
                              void* d_out, int out_size)
{
    const float* x  = (const float*)d_in[0];
    const float* W1 = (const float*)d_in[1];
    const float* b1 = (const float*)d_in[2];
    const float* W2 = (const float*)d_in[3];
    const float* b2 = (const float*)d_in[4];
    float* out = (float*)d_out;

    int B = in_sizes[0] / IN_SZ;            // 131072
    int ytiles = B / (MT * REPS);           // 256

    cudaFuncSetAttribute(mlp16_kernel,
                         cudaFuncAttributeMaxDynamicSharedMemorySize, SMEM_BYTES);
    mlp16_kernel<<<dim3(NHEAD, ytiles), NTHREADS, SMEM_BYTES>>>(x, W1, b1, W2, b2, out);
}

// round 11
// speedup vs baseline: 1.1124x; 1.1124x over previous
#include <cuda_runtime.h>
#include <cstdint>

// ---------------- problem constants ----------------
#define IN_SZ    64
#define HID      128
#define OUT_SZ   64
#define NHEAD    16
#define MT       128          // batch rows per rep
#define REPS     4            // 512 rows per CTA -> grid 4096 (9.2 waves @ 3 CTA/SM)
#define NTHREADS 128          // 4 warps; warp = 32 rows x full width

// ---------------- smem layout (u32 offsets; pitches % 8 == 4 -> conflict-free) ----------------
#define XT0_U   0             // x buf 0: 128 rows x 36 u32
#define XT1_U   4608          // x buf 1
#define W1T_U   9216          // W1^T: 128 rows(n) x 36 u32 (64 k halves)
#define W2T_U   13824         // W2^T:  64 rows(n) x 68 u32 (128 k halves)
#define B1S_U   18176         // 128 f32
#define B2S_U   18304         // 64 f32
#define SMEM_U  18368
#define SMEM_BYTES (SMEM_U * 4)   // 73472 B -> 3 CTAs/SM

#define XPB     144           // x / W1T row pitch bytes
#define HPB     272           // W2T row pitch bytes
#define XP      36
#define HP      68

// ---------------- helpers ----------------
__device__ __forceinline__ uint32_t smem_u32(const void* p) {
    uint32_t a;
    asm("{ .reg .u64 t; cvta.to.shared.u64 t, %1; cvt.u32.u64 %0, t; }"
        : "=r"(a) : "l"(p));
    return a;
}

// pack two f32 -> f16x2 (lo = a, hi = b)
__device__ __forceinline__ uint32_t p2(float a, float b) {
    uint32_t r;
    asm("cvt.rn.f16x2.f32 %0, %1, %2;" : "=r"(r) : "f"(b), "f"(a));
    return r;
}

__device__ __forceinline__ void ldsm4(uint4& d, uint32_t addr) {
    asm volatile("ldmatrix.sync.aligned.m8n8.x4.shared.b16 {%0,%1,%2,%3}, [%4];"
                 : "=r"(d.x), "=r"(d.y), "=r"(d.z), "=r"(d.w) : "r"(addr));
}

// D += A * B  (f16 m16n8k16, row.col, fp32 accum)
__device__ __forceinline__ void mma16(float c[4], const uint4 a, uint32_t b0, uint32_t b1) {
    asm volatile(
        "mma.sync.aligned.m16n8k16.row.col.f32.f16.f16.f32 "
        "{%0,%1,%2,%3}, {%4,%5,%6,%7}, {%8,%9}, {%0,%1,%2,%3};\n"
        : "+f"(c[0]), "+f"(c[1]), "+f"(c[2]), "+f"(c[3])
        : "r"(a.x), "r"(a.y), "r"(a.z), "r"(a.w), "r"(b0), "r"(b1));
}

__device__ __forceinline__ float eluf(float v) {
    return v > 0.0f ? v : (__expf(v) - 1.0f);
}

// ---------------- kernel ----------------
__global__ void __launch_bounds__(NTHREADS, 3)
mlp16_kernel(const float* __restrict__ x,
             const float* __restrict__ W1,
             const float* __restrict__ b1,
             const float* __restrict__ W2,
             const float* __restrict__ b2,
             float* __restrict__ out)
{
    extern __shared__ uint32_t sm[];
    float* b1s = reinterpret_cast<float*>(sm + B1S_U);
    float* b2s = reinterpret_cast<float*>(sm + B2S_U);
    const uint32_t sb = smem_u32(sm);

    const int tid = threadIdx.x;
    const int wid = tid >> 5;          // 0..3 : rows [32*wid, +32)
    const int lid = tid & 31;
    const int g   = lid >> 2;          // 0..7
    const int tc  = lid & 3;           // 0..3
    const int head = blockIdx.x;
    const size_t mbase = (size_t)blockIdx.y * (MT * REPS);

    // ldmatrix per-lane address components
    const int arow = (lid & 7) + (lid & 8);          // A row within 16
    const int akb  = (lid & 16);                     // A k-half byte offset
    const int brow = (lid & 7) + ((lid & 16) >> 1);  // B n-row within 16
    const int bkb  = (lid & 8) << 1;                 // B k-half byte offset

    const uint32_t aX0 = sb + XT0_U * 4 + (wid * 32 + arow) * XPB + akb;
    const uint32_t aX1 = sb + XT1_U * 4 + (wid * 32 + arow) * XPB + akb;
    const uint32_t bW1 = sb + W1T_U * 4 + brow * XPB + bkb;
    const uint32_t bW2 = sb + W2T_U * 4 + brow * HPB + bkb;

    // ---- biases ----
    b1s[tid] = b1[head * HID + tid];
    if (tid < OUT_SZ) b2s[tid] = b2[head * OUT_SZ + tid];

    // ---- stage W1^T (fp16): row n = tid, k = 0..63 ----
    {
        const float* W1h = W1 + (size_t)head * IN_SZ * HID;
        const int n = tid;
        #pragma unroll
        for (int i4 = 0; i4 < 16; i4++) {
            int k0 = i4 * 4;
            float w0 = W1h[(k0 + 0) * HID + n];
            float w1 = W1h[(k0 + 1) * HID + n];
            float w2 = W1h[(k0 + 2) * HID + n];
            float w3 = W1h[(k0 + 3) * HID + n];
            uint2 u;
            u.x = p2(w0, w1);
            u.y = p2(w2, w3);
            *reinterpret_cast<uint2*>(sm + W1T_U + n * XP + 2 * i4) = u;
        }
    }

    // ---- stage W2^T (fp16): row n = tid&63, k = 0..127 ----
    {
        const float* W2h = W2 + (size_t)head * HID * OUT_SZ;
        const int n = tid & 63;
        const int jh = tid >> 6;           // 0..1
        #pragma unroll
        for (int jj = 0; jj < 16; jj++) {
            int j4 = jh * 16 + jj;
            int k0 = j4 * 4;
            float w0 = W2h[(k0 + 0) * OUT_SZ + n];
            float w1 = W2h[(k0 + 1) * OUT_SZ + n];
            float w2 = W2h[(k0 + 2) * OUT_SZ + n];
            float w3 = W2h[(k0 + 3) * OUT_SZ + n];
            uint2 u;
            u.x = p2(w0, w1);
            u.y = p2(w2, w3);
            *reinterpret_cast<uint2*>(sm + W2T_U + n * HP + 2 * j4) = u;
        }
    }

    // ---- prologue: stage x rep 0 into buf 0 ----
    {
        const float4* xt = reinterpret_cast<const float4*>(x + mbase * IN_SZ);
        #pragma unroll
        for (int it = 0; it < 8; it++) {
            int task = it * NTHREADS + tid;    // 0..1023
            int row = task >> 3;
            int q   = task & 7;
            float4 v0 = xt[row * 16 + 2 * q];
            float4 v1 = xt[row * 16 + 2 * q + 1];
            uint4 u;
            u.x = p2(v0.x, v0.y);
            u.y = p2(v0.z, v0.w);
            u.z = p2(v1.x, v1.y);
            u.w = p2(v1.z, v1.w);
            *reinterpret_cast<uint4*>(sm + XT0_U + row * XP + 4 * q) = u;
        }
    }

    #pragma unroll 1
    for (int rep = 0; rep < REPS; rep++) {
        __syncthreads();   // x buf (rep&1) ready; buf (rep+1)&1 free

        const uint32_t aX = (rep & 1) ? aX1 : aX0;
        uint4 A2q[2][8];   // GEMM2 A fragments (built in registers)

        // ---- GEMM1 in two 64-col halves ----
        #pragma unroll
        for (int half = 0; half < 2; half++) {
            float C1[2][8][4];
            #pragma unroll
            for (int mt = 0; mt < 2; mt++)
                #pragma unroll
                for (int t1 = 0; t1 < 8; t1++)
                    #pragma unroll
                    for (int r = 0; r < 4; r++) C1[mt][t1][r] = 0.0f;

            #pragma unroll
            for (int s = 0; s < 4; s++) {          // k16 steps, K=64
                uint4 A0, A1;
                ldsm4(A0, aX + s * 32);
                ldsm4(A1, aX + s * 32 + 16 * XPB);
                #pragma unroll
                for (int tp = 0; tp < 4; tp++) {   // 2 n-tiles per ldsm
                    uint4 Bv;
                    ldsm4(Bv, bW1 + (half * 64 + tp * 16) * XPB + s * 32);
                    mma16(C1[0][2 * tp],     A0, Bv.x, Bv.y);
                    mma16(C1[0][2 * tp + 1], A0, Bv.z, Bv.w);
                    mma16(C1[1][2 * tp],     A1, Bv.x, Bv.y);
                    mma16(C1[1][2 * tp + 1], A1, Bv.z, Bv.w);
                }
            }

            // epilogue1: bias + ELU -> pack directly into GEMM2 A fragments
            #pragma unroll
            for (int mt = 0; mt < 2; mt++)
                #pragma unroll
                for (int t1 = 0; t1 < 8; t1++) {
                    int col = half * 64 + t1 * 8 + 2 * tc;
                    float bA = b1s[col], bB = b1s[col + 1];
                    float v0 = eluf(C1[mt][t1][0] + bA);
                    float v1 = eluf(C1[mt][t1][1] + bB);
                    float v2 = eluf(C1[mt][t1][2] + bA);
                    float v3 = eluf(C1[mt][t1][3] + bB);
                    int s2 = half * 4 + (t1 >> 1);
                    uint32_t lo = p2(v0, v1);     // rows g
                    uint32_t hi = p2(v2, v3);     // rows g+8
                    if ((t1 & 1) == 0) { A2q[mt][s2].x = lo; A2q[mt][s2].y = hi; }
                    else               { A2q[mt][s2].z = lo; A2q[mt][s2].w = hi; }
                }
        }

        // ---- stage x for rep+1 into the other buffer (overlaps GEMM2) ----
        if (rep + 1 < REPS) {
            const float4* xt = reinterpret_cast<const float4*>(
                x + (mbase + (size_t)(rep + 1) * MT) * IN_SZ);
            uint32_t* dst = sm + ((rep & 1) ? XT0_U : XT1_U);
            #pragma unroll
            for (int it = 0; it < 8; it++) {
                int task = it * NTHREADS + tid;
                int row = task >> 3;
                int q   = task & 7;
                float4 v0 = xt[row * 16 + 2 * q];
                float4 v1 = xt[row * 16 + 2 * q + 1];
                uint4 u;
                u.x = p2(v0.x, v0.y);
                u.y = p2(v0.z, v0.w);
                u.z = p2(v1.x, v1.y);
                u.w = p2(v1.z, v1.w);
                *reinterpret_cast<uint4*>(dst + row * XP + 4 * q) = u;
            }
        }

        // ---- GEMM2 in two 32-col n-halves, B prefetched (s+1) ----
        #pragma unroll
        for (int nh2 = 0; nh2 < 2; nh2++) {
            float C2[2][4][4];
            #pragma unroll
            for (int mt = 0; mt < 2; mt++)
                #pragma unroll
                for (int t2 = 0; t2 < 4; t2++)
                    #pragma unroll
                    for (int r = 0; r < 4; r++) C2[mt][t2][r] = 0.0f;

            const uint32_t bB = bW2 + (nh2 * 2) * 16 * HPB;
            uint4 Bc0, Bc1;
            ldsm4(Bc0, bB);
            ldsm4(Bc1, bB + 16 * HPB);

            #pragma unroll
            for (int s = 0; s < 8; s++) {
                uint4 Bn0, Bn1;
                if (s < 7) {
                    ldsm4(Bn0, bB + (s + 1) * 32);
                    ldsm4(Bn1, bB + 16 * HPB + (s + 1) * 32);
                }
                mma16(C2[0][0], A2q[0][s], Bc0.x, Bc0.y);
                mma16(C2[0][1], A2q[0][s], Bc0.z, Bc0.w);
                mma16(C2[0][2], A2q[0][s], Bc1.x, Bc1.y);
                mma16(C2[0][3], A2q[0][s], Bc1.z, Bc1.w);
                mma16(C2[1][0], A2q[1][s], Bc0.x, Bc0.y);
                mma16(C2[1][1], A2q[1][s], Bc0.z, Bc0.w);
                mma16(C2[1][2], A2q[1][s], Bc1.x, Bc1.y);
                mma16(C2[1][3], A2q[1][s], Bc1.z, Bc1.w);
                Bc0 = Bn0;
                Bc1 = Bn1;
            }

            // epilogue2 (this half): + b2 -> out[b, head, :]
            #pragma unroll
            for (int mt = 0; mt < 2; mt++) {
                const size_t rbase = mbase + (size_t)rep * MT + wid * 32 + mt * 16 + g;
                #pragma unroll
                for (int half = 0; half < 2; half++) {
                    const size_t off = (rbase + 8 * half) * (NHEAD * OUT_SZ)
                                     + (size_t)head * OUT_SZ;
                    #pragma unroll
                    for (int t2 = 0; t2 < 4; t2++) {
                        int col = nh2 * 32 + t2 * 8 + 2 * tc;
                        float2 o;
                        o.x = C2[mt][t2][half * 2 + 0] + b2s[col];
                        o.y = C2[mt][t2][half * 2 + 1] + b2s[col + 1];
                        *reinterpret_cast<float2*>(out + off + col) = o;
                    }
                }
            }
        }
    }
}

// ---------------- launch ----------------
extern "C" void kernel_launch(void* const* d_in, const int* in_sizes, int n_in,
                              void* d_out, int out_size)
{
    const float* x  = (const float*)d_in[0];
    const float* W1 = (const float*)d_in[1];
    const float* b1 = (const float*)d_in[2];
    const float* W2 = (const float*)d_in[3];
    const float* b2 = (const float*)d_in[4];
    float* out = (float*)d_out;

    int B = in_sizes[0] / IN_SZ;            // 131072
    int ytiles = B / (MT * REPS);           // 256

    cudaFuncSetAttribute(mlp16_kernel,
                         cudaFuncAttributeMaxDynamicSharedMemorySize, SMEM_BYTES);
    mlp16_kernel<<<dim3(NHEAD, ytiles), NTHREADS, SMEM_BYTES>>>(x, W1, b1, W2, b2, out);
}

// round 12
// speedup vs baseline: 1.4120x; 1.2693x over previous
#include <cuda_runtime.h>
#include <cstdint>

// ---------------- problem constants ----------------
#define IN_SZ    64
#define HID      128
#define OUT_SZ   64
#define NHEAD    16
#define MT       128          // batch rows per rep
#define REPS     4            // 512 rows per CTA -> grid 4096
#define NTHREADS 128          // 4 warps; warp = 32 rows x full width

// ---------------- smem layout (u32 offsets; pitches % 8 == 4 -> conflict-free) ----------------
#define W1T_U   0             // W1^T: 128 rows(n) x 36 u32 (64 k halves, k-permuted)
#define W2T_U   4608          // W2^T:  64 rows(n) x 68 u32 (128 k halves)
#define B1S_U   8960          // 128 f32
#define B2S_U   9088          // 64 f32
#define SMEM_U  9152
#define SMEM_BYTES (SMEM_U * 4)   // 36608 B

#define XPB     144           // W1T row pitch bytes
#define HPB     272           // W2T row pitch bytes
#define XP      36
#define HP      68

// ---------------- helpers ----------------
__device__ __forceinline__ uint32_t smem_u32(const void* p) {
    uint32_t a;
    asm("{ .reg .u64 t; cvta.to.shared.u64 t, %1; cvt.u32.u64 %0, t; }"
        : "=r"(a) : "l"(p));
    return a;
}

// pack two f32 -> f16x2 (lo = a, hi = b)
__device__ __forceinline__ uint32_t p2(float a, float b) {
    uint32_t r;
    asm("cvt.rn.f16x2.f32 %0, %1, %2;" : "=r"(r) : "f"(b), "f"(a));
    return r;
}

__device__ __forceinline__ void ldsm4(uint4& d, uint32_t addr) {
    asm volatile("ldmatrix.sync.aligned.m8n8.x4.shared.b16 {%0,%1,%2,%3}, [%4];"
                 : "=r"(d.x), "=r"(d.y), "=r"(d.z), "=r"(d.w) : "r"(addr));
}

// D += A * B  (f16 m16n8k16, row.col, fp32 accum)
__device__ __forceinline__ void mma16(float c[4], const uint4 a, uint32_t b0, uint32_t b1) {
    asm volatile(
        "mma.sync.aligned.m16n8k16.row.col.f32.f16.f16.f32 "
        "{%0,%1,%2,%3}, {%4,%5,%6,%7}, {%8,%9}, {%0,%1,%2,%3};\n"
        : "+f"(c[0]), "+f"(c[1]), "+f"(c[2]), "+f"(c[3])
        : "r"(a.x), "r"(a.y), "r"(a.z), "r"(a.w), "r"(b0), "r"(b1));
}

__device__ __forceinline__ float eluf(float v) {
    return v > 0.0f ? v : (__expf(v) - 1.0f);
}

// ---------------- kernel ----------------
__global__ void __launch_bounds__(NTHREADS, 3)
mlp16_kernel(const float* __restrict__ x,
             const float* __restrict__ W1,
             const float* __restrict__ b1,
             const float* __restrict__ W2,
             const float* __restrict__ b2,
             float* __restrict__ out)
{
    extern __shared__ uint32_t sm[];
    float* b1s = reinterpret_cast<float*>(sm + B1S_U);
    float* b2s = reinterpret_cast<float*>(sm + B2S_U);
    const uint32_t sb = smem_u32(sm);

    const int tid = threadIdx.x;
    const int wid = tid >> 5;          // 0..3 : rows [32*wid, +32)
    const int lid = tid & 31;
    const int g   = lid >> 2;          // 0..7
    const int tc  = lid & 3;           // 0..3
    const int head = blockIdx.x;
    const size_t mbase = (size_t)blockIdx.y * (MT * REPS);

    // ldmatrix per-lane address components (B fragments)
    const int brow = (lid & 7) + ((lid & 16) >> 1);  // B n-row within 16
    const int bkb  = (lid & 8) << 1;                 // B k-half byte offset

    const uint32_t bW1 = sb + W1T_U * 4 + brow * XPB + bkb;
    const uint32_t bW2 = sb + W2T_U * 4 + brow * HPB + bkb;

    // ---- biases ----
    b1s[tid] = b1[head * HID + tid];
    if (tid < OUT_SZ) b2s[tid] = b2[head * OUT_SZ + tid];

    // ---- stage W1^T (fp16), K-PERMUTED to match float4 A-frag gmem loads ----
    // u32 slot (n, s, q):  tc=q&3, kh=q>>2;  halves = W1[k0][n], W1[k0+1][n]
    // with k0 = 16s + 4tc + 2kh   (π(16s+2tc+b)=16s+4tc+b, π(16s+8+2tc+b)=16s+4tc+2+b)
    {
        const float* W1h = W1 + (size_t)head * IN_SZ * HID;
        const int n = tid;
        #pragma unroll
        for (int s = 0; s < 4; s++)
            #pragma unroll
            for (int q = 0; q < 8; q++) {
                int k0 = 16 * s + 4 * (q & 3) + 2 * (q >> 2);
                float w0 = W1h[(k0 + 0) * HID + n];
                float w1 = W1h[(k0 + 1) * HID + n];
                sm[W1T_U + n * XP + s * 8 + q] = p2(w0, w1);
            }
    }

    // ---- stage W2^T (fp16): row n = tid&63, k = 0..127 (natural order) ----
    {
        const float* W2h = W2 + (size_t)head * HID * OUT_SZ;
        const int n = tid & 63;
        const int jh = tid >> 6;           // 0..1
        #pragma unroll
        for (int jj = 0; jj < 16; jj++) {
            int j4 = jh * 16 + jj;
            int k0 = j4 * 4;
            float w0 = W2h[(k0 + 0) * OUT_SZ + n];
            float w1 = W2h[(k0 + 1) * OUT_SZ + n];
            float w2 = W2h[(k0 + 2) * OUT_SZ + n];
            float w3 = W2h[(k0 + 3) * OUT_SZ + n];
            uint2 u;
            u.x = p2(w0, w1);
            u.y = p2(w2, w3);
            *reinterpret_cast<uint2*>(sm + W2T_U + n * HP + 2 * j4) = u;
        }
    }

    __syncthreads();   // weights + biases visible; NO more barriers below

    #pragma unroll 1
    for (int rep = 0; rep < REPS; rep++) {
        const size_t r0 = mbase + (size_t)rep * MT + wid * 32;

        // ---- load x A-fragments straight from gmem (K-permuted layout) ----
        // lane: rows (g, g+8) of its 16-row tile; cols 16s+4tc .. +3 (one float4)
        uint4 XA[2][4];
        #pragma unroll
        for (int mt = 0; mt < 2; mt++) {
            const float4* plo = reinterpret_cast<const float4*>(
                x + (r0 + mt * 16 + g) * IN_SZ) + tc;
            const float4* phi = reinterpret_cast<const float4*>(
                x + (r0 + mt * 16 + g + 8) * IN_SZ) + tc;
            #pragma unroll
            for (int s = 0; s < 4; s++) {
                float4 f0 = plo[s * 4];
                float4 f1 = phi[s * 4];
                XA[mt][s].x = p2(f0.x, f0.y);
                XA[mt][s].y = p2(f1.x, f1.y);
                XA[mt][s].z = p2(f0.z, f0.w);
                XA[mt][s].w = p2(f1.z, f1.w);
            }
        }

        uint4 A2q[2][8];   // GEMM2 A fragments (built in registers)

        // ---- GEMM1 in two 64-col halves ----
        #pragma unroll
        for (int half = 0; half < 2; half++) {
            float C1[2][8][4];
            #pragma unroll
            for (int mt = 0; mt < 2; mt++)
                #pragma unroll
                for (int t1 = 0; t1 < 8; t1++)
                    #pragma unroll
                    for (int r = 0; r < 4; r++) C1[mt][t1][r] = 0.0f;

            #pragma unroll
            for (int s = 0; s < 4; s++) {          // k16 steps, K=64
                #pragma unroll
                for (int tp = 0; tp < 4; tp++) {   // 2 n-tiles per ldsm
                    uint4 Bv;
                    ldsm4(Bv, bW1 + (half * 64 + tp * 16) * XPB + s * 32);
                    mma16(C1[0][2 * tp],     XA[0][s], Bv.x, Bv.y);
                    mma16(C1[0][2 * tp + 1], XA[0][s], Bv.z, Bv.w);
                    mma16(C1[1][2 * tp],     XA[1][s], Bv.x, Bv.y);
                    mma16(C1[1][2 * tp + 1], XA[1][s], Bv.z, Bv.w);
                }
            }

            // epilogue1: bias + ELU -> pack directly into GEMM2 A fragments
            #pragma unroll
            for (int mt = 0; mt < 2; mt++)
                #pragma unroll
                for (int t1 = 0; t1 < 8; t1++) {
                    int col = half * 64 + t1 * 8 + 2 * tc;
                    float bA = b1s[col], bB = b1s[col + 1];
                    float v0 = eluf(C1[mt][t1][0] + bA);
                    float v1 = eluf(C1[mt][t1][1] + bB);
                    float v2 = eluf(C1[mt][t1][2] + bA);
                    float v3 = eluf(C1[mt][t1][3] + bB);
                    int s2 = half * 4 + (t1 >> 1);
                    uint32_t lo = p2(v0, v1);     // rows g
                    uint32_t hi = p2(v2, v3);     // rows g+8
                    if ((t1 & 1) == 0) { A2q[mt][s2].x = lo; A2q[mt][s2].y = hi; }
                    else               { A2q[mt][s2].z = lo; A2q[mt][s2].w = hi; }
                }
        }

        // ---- GEMM2 in two 32-col n-halves, B prefetched (s+1) ----
        #pragma unroll
        for (int nh2 = 0; nh2 < 2; nh2++) {
            float C2[2][4][4];
            #pragma unroll
            for (int mt = 0; mt < 2; mt++)
                #pragma unroll
                for (int t2 = 0; t2 < 4; t2++)
                    #pragma unroll
                    for (int r = 0; r < 4; r++) C2[mt][t2][r] = 0.0f;

            const uint32_t bB = bW2 + (nh2 * 2) * 16 * HPB;
            uint4 Bc0, Bc1;
            ldsm4(Bc0, bB);
            ldsm4(Bc1, bB + 16 * HPB);

            #pragma unroll
            for (int s = 0; s < 8; s++) {
                uint4 Bn0, Bn1;
                if (s < 7) {
                    ldsm4(Bn0, bB + (s + 1) * 32);
                    ldsm4(Bn1, bB + 16 * HPB + (s + 1) * 32);
                }
                mma16(C2[0][0], A2q[0][s], Bc0.x, Bc0.y);
                mma16(C2[0][1], A2q[0][s], Bc0.z, Bc0.w);
                mma16(C2[0][2], A2q[0][s], Bc1.x, Bc1.y);
                mma16(C2[0][3], A2q[0][s], Bc1.z, Bc1.w);
                mma16(C2[1][0], A2q[1][s], Bc0.x, Bc0.y);
                mma16(C2[1][1], A2q[1][s], Bc0.z, Bc0.w);
                mma16(C2[1][2], A2q[1][s], Bc1.x, Bc1.y);
                mma16(C2[1][3], A2q[1][s], Bc1.z, Bc1.w);
                Bc0 = Bn0;
                Bc1 = Bn1;
            }

            // epilogue2 (this half): + b2 -> out[b, head, :]
            #pragma unroll
            for (int mt = 0; mt < 2; mt++) {
                const size_t rb = r0 + mt * 16 + g;
                #pragma unroll
                for (int half = 0; half < 2; half++) {
                    const size_t off = (rb + 8 * half) * (NHEAD * OUT_SZ)
                                     + (size_t)head * OUT_SZ;
                    #pragma unroll
                    for (int t2 = 0; t2 < 4; t2++) {
                        int col = nh2 * 32 + t2 * 8 + 2 * tc;
                        float2 o;
                        o.x = C2[mt][t2][half * 2 + 0] + b2s[col];
                        o.y = C2[mt][t2][half * 2 + 1] + b2s[col + 1];
                        *reinterpret_cast<float2*>(out + off + col) = o;
                    }
                }
            }
        }
    }
}

// ---------------- launch ----------------
extern "C" void kernel_launch(void* const* d_in, const int* in_sizes, int n_in,
                              void* d_out, int out_size)
{
    const float* x  = (const float*)d_in[0];
    const float* W1 = (const float*)d_in[1];
    const float* b1 = (const float*)d_in[2];
    const float* W2 = (const float*)d_in[3];
    const float* b2 = (const float*)d_in[4];
    float* out = (float*)d_out;

    int B = in_sizes[0] / IN_SZ;            // 131072
    int ytiles = B / (MT * REPS);           // 256

    cudaFuncSetAttribute(mlp16_kernel,
                         cudaFuncAttributeMaxDynamicSharedMemorySize, SMEM_BYTES);
    mlp16_kernel<<<dim3(NHEAD, ytiles), NTHREADS, SMEM_BYTES>>>(x, W1, b1, W2, b2, out);
}